// round 13
// baseline (speedup 1.0000x reference)
#include <cuda_runtime.h>
#include <cstdint>

#define MDIM 4096
#define NDIM 4096
#define KDIM 4096
#define BM 128
#define BN 256
#define BK 32
#define KT (KDIM / BK)          // 128
#define NTHREADS 256            // 8 warps: 2(m) x 4(n), each 64x64 warp tile
#define NSTAGES 3
#define A_STAGE_FLOATS (BM * BK)                   // 4096
#define B_STAGE_FLOATS (BN * BK)                   // 8192
#define STAGE_FLOATS (A_STAGE_FLOATS + B_STAGE_FLOATS)   // 12288 (48KB)
#define SMEM_BYTES (NSTAGES * STAGE_FLOATS * 4)    // 147456

// tf32-rounded, fragment-permuted copies of x and W
__device__ float g_xr[(size_t)MDIM * KDIM];
__device__ float g_wr[(size_t)NDIM * KDIM];

__device__ __forceinline__ void cp_async16(uint32_t saddr, const void* gptr) {
    asm volatile("cp.async.cg.shared.global [%0], [%1], 16;" :: "r"(saddr), "l"(gptr));
}

__device__ __forceinline__ uint32_t f2tf32(float f) {
    uint32_t u;
    asm("cvt.rna.tf32.f32 %0, %1;" : "=r"(u) : "f"(f));
    return u;
}

// volatile: source order IS the schedule (R8 lesson).
__device__ __forceinline__ void mma_tf32(float& c0, float& c1, float& c2, float& c3,
                                         uint32_t a0, uint32_t a1, uint32_t a2, uint32_t a3,
                                         uint32_t b0, uint32_t b1) {
    asm volatile(
        "mma.sync.aligned.m16n8k8.row.col.f32.tf32.tf32.f32 "
        "{%0,%1,%2,%3},{%4,%5,%6,%7},{%8,%9},{%0,%1,%2,%3};"
        : "+f"(c0), "+f"(c1), "+f"(c2), "+f"(c3)
        : "r"(a0), "r"(a1), "r"(a2), "r"(a3), "r"(b0), "r"(b1));
}

// ---- Prepass A (unchanged): round to tf32 + permute to fragment order ----
// g_xr layout: [m_blk(32)][k_blk(128)][m_sub(8)][k_sub(4)][lane(32)][q(4)]
__global__ void __launch_bounds__(256) perm_a_kernel(const float* __restrict__ x) {
    size_t i = (size_t)blockIdx.x * 256 + threadIdx.x;   // float4 index, 4194304 total
    int lane  = (int)(i & 31);
    int k_sub = (int)((i >> 5) & 3);
    int m_sub = (int)((i >> 7) & 7);
    size_t blk = i >> 10;
    int k_blk = (int)(blk & 127);
    int m_blk = (int)(blk >> 7);
    int m = m_blk * 128 + m_sub * 16 + (lane >> 2);
    int k = k_blk * 32 + k_sub * 8 + (lane & 3);
    const float* p = x + (size_t)m * KDIM + k;
    float4 v;
    v.x = __uint_as_float(f2tf32(p[0]));
    v.y = __uint_as_float(f2tf32(p[8 * KDIM]));
    v.z = __uint_as_float(f2tf32(p[4]));
    v.w = __uint_as_float(f2tf32(p[8 * KDIM + 4]));
    reinterpret_cast<float4*>(g_xr)[i] = v;
}

// ---- Prepass B (unchanged): round + permute W ----
// g_wr layout: [n_blk(32)][k_blk(128)][n_sub(16)][k_sub(4)][lane(32)][q(2)]
__global__ void __launch_bounds__(256) perm_b_kernel(const float* __restrict__ W) {
    size_t i = (size_t)blockIdx.x * 256 + threadIdx.x;   // float2 index, 8388608 total
    int lane  = (int)(i & 31);
    int k_sub = (int)((i >> 5) & 3);
    int n_sub = (int)((i >> 7) & 15);
    size_t blk = i >> 11;
    int k_blk = (int)(blk & 127);
    int n_blk = (int)(blk >> 7);
    int n = n_blk * 128 + n_sub * 8 + (lane >> 2);
    int k = k_blk * 32 + k_sub * 8 + (lane & 3);
    const float* p = W + (size_t)n * KDIM + k;
    float2 v;
    v.x = __uint_as_float(f2tf32(p[0]));
    v.y = __uint_as_float(f2tf32(p[4]));
    reinterpret_cast<float2*>(g_wr)[i] = v;
}

// ---- Main GEMM: 128x256 CTA tile, 8 warps of 64x64 ----
__global__ void __launch_bounds__(NTHREADS, 1)
gemm_tf32_frag(const float* __restrict__ bias, float* __restrict__ out) {
    extern __shared__ float smem[];
    const int tid  = threadIdx.x;
    const int lane = tid & 31;
    const int warp = tid >> 5;
    const int wm = warp >> 2;   // 0..1  (64-row slab)
    const int wn = warp & 3;    // 0..3  (64-col slab)
    const int bn = blockIdx.x;  // 0..15 (256-wide)
    const int bm = blockIdx.y;  // 0..31

    const float* gA  = g_xr + (size_t)bm * 128 * 4096;
    const float* gB0 = g_wr + (size_t)(2 * bn) * 128 * 4096;       // n_blk 2bn
    const float* gB1 = g_wr + (size_t)(2 * bn + 1) * 128 * 4096;   // n_blk 2bn+1

    uint32_t sbase;
    asm("{ .reg .u64 t; cvta.to.shared.u64 t, %1; cvt.u32.u64 %0, t; }"
        : "=r"(sbase) : "l"(smem));

    float acc[4][8][4];
    #pragma unroll
    for (int mt = 0; mt < 4; mt++)
        #pragma unroll
        for (int nt = 0; nt < 8; nt++)
            #pragma unroll
            for (int r = 0; r < 4; r++)
                acc[mt][nt][r] = 0.0f;

    // stage layout: A[4096] then B[8192] (two contiguous 4096 halves = n_blks)
    auto fill = [&](int s, int kt) {
        const uint32_t st = sbase + s * STAGE_FLOATS * 4;
        const float* ga  = gA  + (size_t)kt * 4096;
        const float* gb0 = gB0 + (size_t)kt * 4096;
        const float* gb1 = gB1 + (size_t)kt * 4096;
        #pragma unroll
        for (int i = 0; i < 4; i++) {   // A: 1024 float4 / 256 threads
            int c = tid + i * NTHREADS;
            cp_async16(st + c * 16, ga + c * 4);
        }
        #pragma unroll
        for (int i = 0; i < 4; i++) {   // B half 0: 1024 float4
            int c = tid + i * NTHREADS;
            cp_async16(st + 16384 + c * 16, gb0 + c * 4);
        }
        #pragma unroll
        for (int i = 0; i < 4; i++) {   // B half 1: 1024 float4
            int c = tid + i * NTHREADS;
            cp_async16(st + 32768 + c * 16, gb1 + c * 4);
        }
    };

    fill(0, 0);
    asm volatile("cp.async.commit_group;");
    fill(1, 1);
    asm volatile("cp.async.commit_group;");

    const int aoff = wm * 2048 + lane * 4;   // ((wm*4+mt)*4+ks)<<7 + lane*4
    const int boff = wn * 2048 + lane * 2;   // ((wn*8+nt)*4+ks)<<6 + lane*2

    int s_cur = 0, s_next = 2;
    for (int kt = 0; kt < KT; ++kt) {
        asm volatile("cp.async.wait_group 1;" ::: "memory");
        __syncthreads();   // stage s_cur ready; all warps finished previous compute

        if (kt + 2 < KT) fill(s_next, kt + 2);
        asm volatile("cp.async.commit_group;");

        const float* bufA = smem + s_cur * STAGE_FLOATS + aoff;
        const float* bufB = smem + s_cur * STAGE_FLOATS + A_STAGE_FLOATS + boff;

        // software-pipelined over ks: load ks+1 frags before ks's MMA wall
        float4 afc[4], afn[4];
        float2 bfc[8], bfn[8];

        #pragma unroll
        for (int mt = 0; mt < 4; mt++)
            afc[mt] = *reinterpret_cast<const float4*>(bufA + (mt << 9));
        #pragma unroll
        for (int nt = 0; nt < 8; nt++)
            bfc[nt] = *reinterpret_cast<const float2*>(bufB + (nt << 8));

        #pragma unroll
        for (int ks = 0; ks < 4; ++ks) {
            if (ks < 3) {
                #pragma unroll
                for (int mt = 0; mt < 4; mt++)
                    afn[mt] = *reinterpret_cast<const float4*>(
                        bufA + (mt << 9) + ((ks + 1) << 7));
                #pragma unroll
                for (int nt = 0; nt < 8; nt++)
                    bfn[nt] = *reinterpret_cast<const float2*>(
                        bufB + (nt << 8) + ((ks + 1) << 6));
            }

            #pragma unroll
            for (int mt = 0; mt < 4; mt++)
                #pragma unroll
                for (int nt = 0; nt < 8; nt++)
                    mma_tf32(acc[mt][nt][0], acc[mt][nt][1], acc[mt][nt][2], acc[mt][nt][3],
                             __float_as_uint(afc[mt].x), __float_as_uint(afc[mt].y),
                             __float_as_uint(afc[mt].z), __float_as_uint(afc[mt].w),
                             __float_as_uint(bfc[nt].x), __float_as_uint(bfc[nt].y));

            #pragma unroll
            for (int mt = 0; mt < 4; mt++) afc[mt] = afn[mt];
            #pragma unroll
            for (int nt = 0; nt < 8; nt++) bfc[nt] = bfn[nt];
        }

        s_cur  = (s_cur  == NSTAGES - 1) ? 0 : s_cur + 1;
        s_next = (s_next == NSTAGES - 1) ? 0 : s_next + 1;
    }

    // Epilogue: bias + float2 stores
    const int lr = lane >> 2;
    const int lc = lane & 3;
    const int gm0 = bm * BM + wm * 64;
    const int gn0 = bn * BN + wn * 64;

    #pragma unroll
    for (int mt = 0; mt < 4; mt++) {
        #pragma unroll
        for (int nt = 0; nt < 8; nt++) {
            int r  = gm0 + mt * 16 + lr;
            int cn = gn0 + nt * 8 + lc * 2;
            float2 bb = *reinterpret_cast<const float2*>(bias + cn);
            float2 v0 = make_float2(acc[mt][nt][0] + bb.x, acc[mt][nt][1] + bb.y);
            float2 v1 = make_float2(acc[mt][nt][2] + bb.x, acc[mt][nt][3] + bb.y);
            *reinterpret_cast<float2*>(out + (size_t)r * NDIM + cn) = v0;
            *reinterpret_cast<float2*>(out + (size_t)(r + 8) * NDIM + cn) = v1;
        }
    }
}

extern "C" void kernel_launch(void* const* d_in, const int* in_sizes, int n_in,
                              void* d_out, int out_size) {
    const float* x = (const float*)d_in[0];
    const float* W = (const float*)d_in[1];
    const float* b = (const float*)d_in[2];
    float* out = (float*)d_out;

    perm_a_kernel<<<16384, 256>>>(x);   // 4194304 float4
    perm_b_kernel<<<32768, 256>>>(W);   // 8388608 float2

    cudaFuncSetAttribute(gemm_tf32_frag,
                         cudaFuncAttributeMaxDynamicSharedMemorySize, SMEM_BYTES);
    dim3 grid(NDIM / BN, MDIM / BM);    // (16, 32)
    gemm_tf32_frag<<<grid, NTHREADS, SMEM_BYTES>>>(b, out);
}

// round 14
// speedup vs baseline: 1.2902x; 1.2902x over previous
#include <cuda_runtime.h>
#include <cstdint>

#define MDIM 4096
#define NDIM 4096
#define KDIM 4096
#define BM 128
#define BN 128
#define BK 32
#define KT (KDIM / BK)          // 128
#define NTHREADS 128            // 4 warps, each 64x64 warp tile
#define NSTAGES 3
#define STAGE_FLOATS (2 * BM * BK)                 // 8192 (A 4096 + B 4096)
#define SMEM_BYTES (NSTAGES * STAGE_FLOATS * 4)    // 98304

// tf32-rounded, fragment-permuted copies of x and W
__device__ float g_xr[(size_t)MDIM * KDIM];
__device__ float g_wr[(size_t)NDIM * KDIM];

__device__ __forceinline__ void cp_async16(uint32_t saddr, const void* gptr) {
    asm volatile("cp.async.cg.shared.global [%0], [%1], 16;" :: "r"(saddr), "l"(gptr));
}

__device__ __forceinline__ uint32_t f2tf32(float f) {
    uint32_t u;
    asm("cvt.rna.tf32.f32 %0, %1;" : "=r"(u) : "f"(f));
    return u;
}

// volatile: source order IS the schedule (R8 lesson).
__device__ __forceinline__ void mma_tf32(float& c0, float& c1, float& c2, float& c3,
                                         uint32_t a0, uint32_t a1, uint32_t a2, uint32_t a3,
                                         uint32_t b0, uint32_t b1) {
    asm volatile(
        "mma.sync.aligned.m16n8k8.row.col.f32.tf32.tf32.f32 "
        "{%0,%1,%2,%3},{%4,%5,%6,%7},{%8,%9},{%0,%1,%2,%3};"
        : "+f"(c0), "+f"(c1), "+f"(c2), "+f"(c3)
        : "r"(a0), "r"(a1), "r"(a2), "r"(a3), "r"(b0), "r"(b1));
}

// ---- Fused prepass: round to tf32 + permute BOTH matrices ----
// First 4194304 float4-chunks: A (g_xr layout [m_blk][k_blk][m_sub][k_sub][lane][q4])
// Next  8388608 float2-chunks: B (g_wr layout [n_blk][k_blk][n_sub][k_sub][lane][q2])
// Blocks are entirely in one branch (branch-uniform at block granularity).
#define A_CHUNKS 4194304
__global__ void __launch_bounds__(256) perm_ab_kernel(const float* __restrict__ x,
                                                      const float* __restrict__ W) {
    size_t i = (size_t)blockIdx.x * 256 + threadIdx.x;
    if (i < A_CHUNKS) {
        int lane  = (int)(i & 31);
        int k_sub = (int)((i >> 5) & 3);
        int m_sub = (int)((i >> 7) & 7);
        size_t blk = i >> 10;
        int k_blk = (int)(blk & 127);
        int m_blk = (int)(blk >> 7);
        int m = m_blk * 128 + m_sub * 16 + (lane >> 2);
        int k = k_blk * 32 + k_sub * 8 + (lane & 3);
        const float* p = x + (size_t)m * KDIM + k;
        float4 v;
        v.x = __uint_as_float(f2tf32(p[0]));
        v.y = __uint_as_float(f2tf32(p[8 * KDIM]));
        v.z = __uint_as_float(f2tf32(p[4]));
        v.w = __uint_as_float(f2tf32(p[8 * KDIM + 4]));
        reinterpret_cast<float4*>(g_xr)[i] = v;
    } else {
        size_t j = i - A_CHUNKS;           // float2 index, 8388608 total
        int lane  = (int)(j & 31);
        int k_sub = (int)((j >> 5) & 3);
        int n_sub = (int)((j >> 7) & 15);
        size_t blk = j >> 11;
        int k_blk = (int)(blk & 127);
        int n_blk = (int)(blk >> 7);
        int n = n_blk * 128 + n_sub * 8 + (lane >> 2);
        int k = k_blk * 32 + k_sub * 8 + (lane & 3);
        const float* p = W + (size_t)n * KDIM + k;
        float2 v;
        v.x = __uint_as_float(f2tf32(p[0]));
        v.y = __uint_as_float(f2tf32(p[4]));
        reinterpret_cast<float2*>(g_wr)[j] = v;
    }
}

// ---- Main GEMM: 4 warps, 64x64 warp tiles ----
__global__ void __launch_bounds__(NTHREADS, 2)
gemm_tf32_frag(const float* __restrict__ bias, float* __restrict__ out) {
    extern __shared__ float smem[];
    const int tid  = threadIdx.x;
    const int lane = tid & 31;
    const int warp = tid >> 5;
    const int wm = warp >> 1;   // 0..1  (64-row slab)
    const int wn = warp & 1;    // 0..1  (64-col slab)
    const int bn = blockIdx.x;
    const int bm = blockIdx.y;

    const float* gA = g_xr + (size_t)bm * 128 * 4096;
    const float* gB = g_wr + (size_t)bn * 128 * 4096;

    uint32_t sbase;
    asm("{ .reg .u64 t; cvta.to.shared.u64 t, %1; cvt.u32.u64 %0, t; }"
        : "=r"(sbase) : "l"(smem));

    float acc[4][8][4];
    #pragma unroll
    for (int mt = 0; mt < 4; mt++)
        #pragma unroll
        for (int nt = 0; nt < 8; nt++)
            #pragma unroll
            for (int r = 0; r < 4; r++)
                acc[mt][nt][r] = 0.0f;

    auto fill = [&](int s, int kt) {
        const uint32_t st = sbase + s * STAGE_FLOATS * 4;
        const float* ga = gA + (size_t)kt * 4096;
        const float* gb = gB + (size_t)kt * 4096;
        #pragma unroll
        for (int i = 0; i < 8; i++) {   // A: 1024 float4 / 128 threads
            int c = tid + i * NTHREADS;
            cp_async16(st + c * 16, ga + c * 4);
        }
        #pragma unroll
        for (int i = 0; i < 8; i++) {   // B
            int c = tid + i * NTHREADS;
            cp_async16(st + 16384 + c * 16, gb + c * 4);
        }
    };

    fill(0, 0);
    asm volatile("cp.async.commit_group;");
    fill(1, 1);
    asm volatile("cp.async.commit_group;");

    const int aoff = wm * 2048 + lane * 4;   // ((wm*4+mt)*4+ks)<<7 + lane*4
    const int boff = wn * 2048 + lane * 2;   // ((wn*8+nt)*4+ks)<<6 + lane*2

    int s_cur = 0, s_next = 2;
    for (int kt = 0; kt < KT; ++kt) {
        asm volatile("cp.async.wait_group 1;" ::: "memory");
        __syncthreads();   // stage s_cur ready; all warps finished previous compute

        const float* bufA = smem + s_cur * STAGE_FLOATS + aoff;
        const float* bufB = smem + s_cur * STAGE_FLOATS + 4096 + boff;

        // Issue ks0 fragment loads BEFORE the cp.async fill burst so the
        // tensor pipe restarts without waiting behind the LSU issue wall.
        float4 afc[4], afn[4];
        float2 bfc[8], bfn[8];

        #pragma unroll
        for (int mt = 0; mt < 4; mt++)
            afc[mt] = *reinterpret_cast<const float4*>(bufA + (mt << 9));
        #pragma unroll
        for (int nt = 0; nt < 8; nt++)
            bfc[nt] = *reinterpret_cast<const float2*>(bufB + (nt << 8));

        if (kt + 2 < KT) fill(s_next, kt + 2);
        asm volatile("cp.async.commit_group;");

        #pragma unroll
        for (int ks = 0; ks < 4; ++ks) {
            if (ks < 3) {
                #pragma unroll
                for (int mt = 0; mt < 4; mt++)
                    afn[mt] = *reinterpret_cast<const float4*>(
                        bufA + (mt << 9) + ((ks + 1) << 7));
                #pragma unroll
                for (int nt = 0; nt < 8; nt++)
                    bfn[nt] = *reinterpret_cast<const float2*>(
                        bufB + (nt << 8) + ((ks + 1) << 6));
            }

            #pragma unroll
            for (int mt = 0; mt < 4; mt++)
                #pragma unroll
                for (int nt = 0; nt < 8; nt++)
                    mma_tf32(acc[mt][nt][0], acc[mt][nt][1], acc[mt][nt][2], acc[mt][nt][3],
                             __float_as_uint(afc[mt].x), __float_as_uint(afc[mt].y),
                             __float_as_uint(afc[mt].z), __float_as_uint(afc[mt].w),
                             __float_as_uint(bfc[nt].x), __float_as_uint(bfc[nt].y));

            #pragma unroll
            for (int mt = 0; mt < 4; mt++) afc[mt] = afn[mt];
            #pragma unroll
            for (int nt = 0; nt < 8; nt++) bfc[nt] = bfn[nt];
        }

        s_cur  = (s_cur  == NSTAGES - 1) ? 0 : s_cur + 1;
        s_next = (s_next == NSTAGES - 1) ? 0 : s_next + 1;
    }

    // Epilogue: bias + float2 stores
    const int lr = lane >> 2;
    const int lc = lane & 3;
    const int gm0 = bm * BM + wm * 64;
    const int gn0 = bn * BN + wn * 64;

    #pragma unroll
    for (int mt = 0; mt < 4; mt++) {
        #pragma unroll
        for (int nt = 0; nt < 8; nt++) {
            int r  = gm0 + mt * 16 + lr;
            int cn = gn0 + nt * 8 + lc * 2;
            float2 bb = *reinterpret_cast<const float2*>(bias + cn);
            float2 v0 = make_float2(acc[mt][nt][0] + bb.x, acc[mt][nt][1] + bb.y);
            float2 v1 = make_float2(acc[mt][nt][2] + bb.x, acc[mt][nt][3] + bb.y);
            *reinterpret_cast<float2*>(out + (size_t)r * NDIM + cn) = v0;
            *reinterpret_cast<float2*>(out + (size_t)(r + 8) * NDIM + cn) = v1;
        }
    }
}

extern "C" void kernel_launch(void* const* d_in, const int* in_sizes, int n_in,
                              void* d_out, int out_size) {
    const float* x = (const float*)d_in[0];
    const float* W = (const float*)d_in[1];
    const float* b = (const float*)d_in[2];
    float* out = (float*)d_out;

    perm_ab_kernel<<<49152, 256>>>(x, W);   // A: 16384 blocks, B: 32768 blocks

    cudaFuncSetAttribute(gemm_tf32_frag,
                         cudaFuncAttributeMaxDynamicSharedMemorySize, SMEM_BYTES);
    dim3 grid(NDIM / BN, MDIM / BM);    // (32, 32)
    gemm_tf32_frag<<<grid, NTHREADS, SMEM_BYTES>>>(b, out);
}